// round 3
// baseline (speedup 1.0000x reference)
#include <cuda_runtime.h>
#include <math.h>
#include <stdint.h>

// ============================================================================
// AttnBlock: SE(3)-attention edge softmax, D=2, C=2.
//  - radial MLP = scalar piecewise-linear function of dist -> 8192-pt LUT.
//    BN stats: layer1 analytic, layer2 via exact per-bin moment histogram.
//  - main kernel: warp per edge, coalesced wj loads (1.04 GB = HBM roofline),
//    compile-time index decode for the 259-element contraction.
// ============================================================================

#define NB     2048
#define NLUT   8192
#define LUTROW 80
#define NMAX   50048
#define EPSV   1e-5f

__device__ float  g_hist[3 * NB];              // count | sum d | sum d^2
__device__ float  g_AB[180];                   // layer1 affine A[90], B[90]
__device__ double g_stats[540];                // layer2 (sum, sumsq) per (p,v)
__device__ float  g_bn2[540];                  // layer2 bn scale[270], shift[270]
__device__ float  g_lut[(size_t)(NLUT + 1) * LUTROW];
__device__ float  g_node[(size_t)NMAX * 36];   // per node: q[18] | f[18]
__device__ float  g_s[NMAX];                   // segment sums

__constant__ int c_Roff4[10] = {0, 4, 8, 12, 16, 28, 40, 44, 56, 76};

// ---------------------------------------------------------------------------
__global__ void k_zero() {
    int i = blockIdx.x * blockDim.x + threadIdx.x;
    int st = gridDim.x * blockDim.x;
    for (int t = i; t < NMAX; t += st)   g_s[t] = 0.f;
    for (int t = i; t < 3 * NB; t += st) g_hist[t] = 0.f;
    for (int t = i; t < 540; t += st)    g_stats[t] = 0.0;
}

// q = einsum('oi,nik->nok', wq[k], f[k]) concat (18 floats), f concat (18)
__global__ void k_node(const float* __restrict__ f0, const float* __restrict__ f1,
                       const float* __restrict__ f2, const float* __restrict__ wq, int N) {
    int n = blockIdx.x * blockDim.x + threadIdx.x;
    if (n >= N) return;
    const float* F0 = f0 + (size_t)n * 2;
    const float* F1 = f1 + (size_t)n * 6;
    const float* F2 = f2 + (size_t)n * 10;
    float* o_ = g_node + (size_t)n * 36;
#pragma unroll
    for (int o = 0; o < 2; o++) {
        o_[o * 9 + 0] = wq[0 + o * 2 + 0] * F0[0] + wq[0 + o * 2 + 1] * F0[1];
#pragma unroll
        for (int m = 0; m < 3; m++)
            o_[o * 9 + 1 + m] = wq[4 + o * 2 + 0] * F1[m] + wq[4 + o * 2 + 1] * F1[3 + m];
#pragma unroll
        for (int m = 0; m < 5; m++)
            o_[o * 9 + 4 + m] = wq[8 + o * 2 + 0] * F2[m] + wq[8 + o * 2 + 1] * F2[5 + m];
    }
#pragma unroll
    for (int i = 0; i < 2; i++)  o_[18 + i] = F0[i];
#pragma unroll
    for (int i = 0; i < 6; i++)  o_[20 + i] = F1[i];
#pragma unroll
    for (int i = 0; i < 10; i++) o_[26 + i] = F2[i];
}

__global__ void k_hist(const float* __restrict__ dist, int E) {
    __shared__ float h[3 * NB];
    for (int i = threadIdx.x; i < 3 * NB; i += blockDim.x) h[i] = 0.f;
    __syncthreads();
    int i = blockIdx.x * blockDim.x + threadIdx.x, st = gridDim.x * blockDim.x;
    for (int e = i; e < E; e += st) {
        float d = dist[e];
        int b = (int)(d * (float)NB);
        b = max(0, min(NB - 1, b));
        atomicAdd(&h[b], 1.f);
        atomicAdd(&h[NB + b], d);
        atomicAdd(&h[2 * NB + b], d * d);
    }
    __syncthreads();
    for (int j = threadIdx.x; j < 3 * NB; j += blockDim.x)
        if (h[j] != 0.f) atomicAdd(&g_hist[j], h[j]);
}

// dist mean/var (double) + layer1 BN-folded affine per (p,u)
__global__ void k_distmv(const float* __restrict__ rW1, const float* __restrict__ rg1,
                         const float* __restrict__ rbb1, int E) {
    __shared__ double rc[256], r1[256], r2[256];
    __shared__ float smu, svar;
    int t = threadIdx.x;
    double c = 0, s1 = 0, s2 = 0;
    for (int b = t; b < NB; b += 256) {
        c  += (double)g_hist[b];
        s1 += (double)g_hist[NB + b];
        s2 += (double)g_hist[2 * NB + b];
    }
    rc[t] = c; r1[t] = s1; r2[t] = s2;
    __syncthreads();
    for (int o = 128; o > 0; o >>= 1) {
        if (t < o) { rc[t] += rc[t + o]; r1[t] += r1[t + o]; r2[t] += r2[t + o]; }
        __syncthreads();
    }
    if (t == 0) {
        double mu  = r1[0] / (double)E;
        double var = r2[0] / (double)E - mu * mu;
        if (var < 0) var = 0;
        smu = (float)mu; svar = (float)var;
    }
    __syncthreads();
    if (t < 90) {
        float w = rW1[t], gi = rg1[t];
        float inv = rsqrtf(svar * w * w + EPSV);
        g_AB[t]      = w * gi * inv;                 // slope  (b1 cancels in BN)
        g_AB[90 + t] = rbb1[t] - w * smu * gi * inv; // intercept
    }
}

// Layer2 BN stats: exact per-bin affine evaluation using bin moments.
// grid = NB/16 blocks, 288 threads
__global__ void k_stats(const float* __restrict__ rW2, const float* __restrict__ rb2) {
    __shared__ float sA[90], sB[90];
    int t = threadIdx.x;
    if (t < 90) { sA[t] = g_AB[t]; sB[t] = g_AB[90 + t]; }
    __syncthreads();
    if (t >= 270) return;
    int p = t / 30;
    double s1 = 0, s2 = 0;
    int b0 = blockIdx.x * 16;
    for (int bb = 0; bb < 16; bb++) {
        int b = b0 + bb;
        float cnt = g_hist[b];
        if (cnt == 0.f) continue;
        float m1 = g_hist[NB + b], m2 = g_hist[2 * NB + b];
        float dc = ((float)b + 0.5f) * (1.0f / (float)NB);
        float alpha = rb2[t], beta = 0.f;
#pragma unroll
        for (int u = 0; u < 10; u++) {
            float A = sA[p * 10 + u], Bv = sB[p * 10 + u];
            if (fmaf(A, dc, Bv) > 0.f) {
                float w = rW2[p * 300 + (t - p * 30) * 10 + u];
                alpha = fmaf(w, Bv, alpha);
                beta  = fmaf(w, A,  beta);
            }
        }
        double a = alpha, be = beta;
        s1 += a * (double)cnt + be * (double)m1;
        s2 += a * a * (double)cnt + 2.0 * a * be * (double)m1 + be * be * (double)m2;
    }
    atomicAdd(&g_stats[2 * t],     s1);
    atomicAdd(&g_stats[2 * t + 1], s2);
}

__global__ void k_bn2(const float* __restrict__ rg2, const float* __restrict__ rbb2, int E) {
    int t = threadIdx.x;
    if (t < 270) {
        double mean = g_stats[2 * t] / (double)E;
        double var  = g_stats[2 * t + 1] / (double)E - mean * mean;
        if (var < 0) var = 0;
        float sc = rg2[t] * rsqrtf((float)var + EPSV);
        g_bn2[t]       = sc;
        g_bn2[270 + t] = rbb2[t] - (float)mean * sc;
    }
}

// Build LUT rows: full radial eval at NLUT+1 points. grid=NLUT+1, 288 thr.
__global__ void k_lut(const float* __restrict__ rW2, const float* __restrict__ rb2,
                      const float* __restrict__ rW3, const float* __restrict__ rb3) {
    __shared__ float h1[90], h2[272];
    int t = threadIdx.x;
    float d = (float)blockIdx.x * (1.0f / (float)NLUT);
    if (t < 90) h1[t] = fmaxf(0.f, fmaf(g_AB[t], d, g_AB[90 + t]));
    __syncthreads();
    if (t < 270) {
        int p = t / 30;
        float z = rb2[t];
#pragma unroll
        for (int u = 0; u < 10; u++)
            z = fmaf(rW2[p * 300 + (t - p * 30) * 10 + u], h1[p * 10 + u], z);
        h2[t] = fmaxf(0.f, fmaf(z, g_bn2[t], g_bn2[270 + t]));
    }
    __syncthreads();
    if (t < LUTROW) {
        float R = 0.f;
        if (t < 76) {
            int p = 0;
#pragma unroll
            for (int pp = 1; pp < 9; pp++) if (t >= c_Roff4[pp]) p = pp;
            int r = t - c_Roff4[p];
            R = rb3[p * 20 + r];
#pragma unroll
            for (int v = 0; v < 30; v++)
                R = fmaf(rW3[p * 600 + r * 30 + v], h2[p * 30 + v], R);
        }
        g_lut[(size_t)blockIdx.x * LUTROW + t] = R;
    }
}

// -------- main kernel helpers ----------------------------------------------
__device__ constexpr int roffc(int K, int L) {
    int r = 0;
    for (int p = 0; p < L * 3 + K; p++) {
        int k = p % 3, l = p / 3;
        r += 4 * (2 * (k < l ? k : l) + 1);
    }
    return r;
}

// shared layout per warp: [0..76) R, [76..94) q, [94..112) f, [112..162) B
template <int K, int L>
__device__ __forceinline__ float do_p(const float* __restrict__ wj, int e,
                                      float* sh, int lane) {
    constexpr int J    = 2 * (K < L ? K : L) + 1;
    constexpr int K2   = 2 * K + 1;
    constexpr int L2   = 2 * L + 1;
    constexpr int SZ   = J * L2 * K2;
    constexpr int BSZ  = J * 2 * K2;
    constexpr int ROFF = roffc(K, L);
    constexpr int FOFF = (K == 0) ? 0 : ((K == 1) ? 2 : 8);
    constexpr int LOFF = (L == 0) ? 0 : ((L == 1) ? 1 : 4);

    const float* R = sh;
    const float* q = sh + 76;
    const float* f = sh + 94;
    float* B = sh + 112;

    for (int idx = lane; idx < BSZ; idx += 32) {
        int mk = idx % K2, jo = idx / K2;
        B[idx] = R[ROFF + jo * 2] * f[FOFF + mk] +
                 R[ROFF + jo * 2 + 1] * f[FOFF + K2 + mk];
    }
    __syncwarp();

    float acc = 0.f;
    const float* wp = wj + (size_t)e * SZ;
    for (int pos = lane; pos < SZ; pos += 32) {
        float w = wp[pos];
        int mk = pos % K2;
        int r  = pos / K2;
        int ml = r % L2;
        int j  = r / L2;
        int b0 = (j * 2) * K2 + mk;
        acc = fmaf(w, q[LOFF + ml] * B[b0] + q[9 + LOFF + ml] * B[b0 + K2], acc);
    }
    __syncwarp();
    return acc;
}

__global__ void __launch_bounds__(256) k_main(
    const int* __restrict__ dst, const float* __restrict__ dist,
    const float* __restrict__ w00, const float* __restrict__ w01,
    const float* __restrict__ w02, const float* __restrict__ w10,
    const float* __restrict__ w11, const float* __restrict__ w12,
    const float* __restrict__ w20, const float* __restrict__ w21,
    const float* __restrict__ w22,
    float* __restrict__ eout, int E) {
    __shared__ float S[8 * 168];
    int lane = threadIdx.x & 31;
    float* sh = S + (threadIdx.x >> 5) * 168;

    int gw = (int)((blockIdx.x * blockDim.x + threadIdx.x) >> 5);
    int nw = (int)((gridDim.x * blockDim.x) >> 5);

    for (int e = gw; e < E; e += nw) {
        int nd = dst[e];
        float d = dist[e];

        const float* np = g_node + (size_t)nd * 36;
        for (int i = lane; i < 36; i += 32) sh[76 + i] = np[i];

        float td = d * (float)NLUT;
        int i0 = (int)td;
        i0 = max(0, min(NLUT - 1, i0));
        float fr = td - (float)i0;
        const float* L0 = g_lut + (size_t)i0 * LUTROW;
        for (int i = lane; i < 76; i += 32) {
            float r0 = L0[i], r1 = L0[LUTROW + i];
            sh[i] = fmaf(fr, r1 - r0, r0);
        }
        __syncwarp();

        // wj{k}{l} arrays: (k,l) order — wKL below is wj with k=K, l=L
        float acc = 0.f;
        acc += do_p<0, 0>(w00, e, sh, lane);
        acc += do_p<1, 0>(w10, e, sh, lane);
        acc += do_p<2, 0>(w20, e, sh, lane);
        acc += do_p<0, 1>(w01, e, sh, lane);
        acc += do_p<1, 1>(w11, e, sh, lane);
        acc += do_p<2, 1>(w21, e, sh, lane);
        acc += do_p<0, 2>(w02, e, sh, lane);
        acc += do_p<1, 2>(w12, e, sh, lane);
        acc += do_p<2, 2>(w22, e, sh, lane);

#pragma unroll
        for (int o = 16; o > 0; o >>= 1)
            acc += __shfl_xor_sync(0xFFFFFFFFu, acc, o);

        if (lane == 0) {
            float ev = expf(acc);
            eout[e] = ev;
            atomicAdd(&g_s[nd], ev);
        }
        __syncwarp();
    }
}

__global__ void k_div(const int* __restrict__ dst, float* __restrict__ out, int E) {
    int e = blockIdx.x * blockDim.x + threadIdx.x;
    if (e < E) out[e] = out[e] / g_s[dst[e]];
}

// ---------------------------------------------------------------------------
extern "C" void kernel_launch(void* const* d_in, const int* in_sizes, int n_in,
                              void* d_out, int out_size) {
    int b = (n_in == 26) ? 1 : 0;  // leading num_nodes scalar if present
    const int*   dst  = (const int*)d_in[b + 0];
    const float* dist = (const float*)d_in[b + 1];
    const float* f0   = (const float*)d_in[b + 2];
    const float* f1   = (const float*)d_in[b + 3];
    const float* f2   = (const float*)d_in[b + 4];
    const float* wq   = (const float*)d_in[b + 5];
    // wj{k}{l} at b+6 + k*3 + l
    const float* wj[9];
    for (int i = 0; i < 9; i++) wj[i] = (const float*)d_in[b + 6 + i];
    const float* rW1  = (const float*)d_in[b + 15];
    const float* rg1  = (const float*)d_in[b + 17];
    const float* rbb1 = (const float*)d_in[b + 18];
    const float* rW2  = (const float*)d_in[b + 19];
    const float* rb2  = (const float*)d_in[b + 20];
    const float* rg2  = (const float*)d_in[b + 21];
    const float* rbb2 = (const float*)d_in[b + 22];
    const float* rW3  = (const float*)d_in[b + 23];
    const float* rb3  = (const float*)d_in[b + 24];

    int E = in_sizes[b + 0];
    int N = in_sizes[b + 2] / 2;
    float* out = (float*)d_out;

    k_zero<<<256, 256>>>();
    k_node<<<(N + 255) / 256, 256>>>(f0, f1, f2, wq, N);
    k_hist<<<1024, 256>>>(dist, E);
    k_distmv<<<1, 256>>>(rW1, rg1, rbb1, E);
    k_stats<<<NB / 16, 288>>>(rW2, rb2);
    k_bn2<<<1, 288>>>(rg2, rbb2, E);
    k_lut<<<NLUT + 1, 288>>>(rW2, rb2, rW3, rb3);
    // w00=wj(k0,l0), w01=wj(k0,l1)... index k*3+l
    k_main<<<2960, 256>>>(dst, dist,
                          wj[0], wj[1], wj[2],
                          wj[3], wj[4], wj[5],
                          wj[6], wj[7], wj[8],
                          out, E);
    k_div<<<(E + 255) / 256, 256>>>(dst, out, E);
}

// round 4
// speedup vs baseline: 1.8696x; 1.8696x over previous
#include <cuda_runtime.h>
#include <math.h>
#include <stdint.h>

// ============================================================================
// AttnBlock: SE(3)-attention edge softmax, D=2, C=2.
//  - radial MLP = scalar piecewise-linear function of dist -> 8192-pt LUT
//    (layer1 BN analytic, layer2 BN via exact per-bin moment histogram).
//  - main kernel: warp per edge, register-resident per-lane index tables,
//    vectorized LDS, 3 syncwarps/edge.
// ============================================================================

#define NB     2048
#define NLUT   8192
#define NMAX   50048
#define EPSV   1e-5f

__device__ float  g_hist[3 * NB];
__device__ float  g_AB[180];
__device__ double g_stats[540];
__device__ float  g_bn2[540];
__device__ float  g_lut2[(size_t)(NLUT + 1) * 160];  // [i0][i<80][{row i0, row i0+1}]
__device__ float  g_node[(size_t)NMAX * 36];         // qi[18] | fi[18], interleaved pairs
__device__ float  g_s[NMAX];
__device__ uchar4 g_ct[288];   // contraction slot -> (arr, off, b2pair, qpair)
__device__ uchar4 g_bt[96];    // B-build slot -> (Rquad, fpos, b2pair, 0)

__constant__ int c_Roff4[9] = {0, 4, 8, 12, 16, 28, 40, 44, 56}; // p = l*3+k
__constant__ int c_SZ[9]    = {1, 3, 5, 3, 27, 45, 5, 45, 125};  // a = k*3+l

// ---------------------------------------------------------------------------
__global__ void k_zero() {
    int i = blockIdx.x * blockDim.x + threadIdx.x;
    int st = gridDim.x * blockDim.x;
    for (int t = i; t < NMAX; t += st)   g_s[t] = 0.f;
    for (int t = i; t < 3 * NB; t += st) g_hist[t] = 0.f;
    for (int t = i; t < 540; t += st)    g_stats[t] = 0.0;
}

__global__ void k_tables() {
    if (threadIdx.x || blockIdx.x) return;
    const int LOFF2[3] = {0, 1, 4};
    const int FOFF2[3] = {0, 1, 4};
    // pair base per array a (cumsum of J*K2 in a-order)
    int PB[9]; int pb = 0;
    for (int a = 0; a < 9; a++) {
        int k = a / 3, l = a % 3;
        int J = 2 * min(k, l) + 1, K2 = 2 * k + 1;
        PB[a] = pb; pb += J * K2;
    }
    int flat = 0;
    for (int a = 0; a < 9; a++) {
        int k = a / 3, l = a % 3;
        int J = 2 * min(k, l) + 1, K2 = 2 * k + 1, L2 = 2 * l + 1;
        int SZ = J * L2 * K2;
        for (int t = 0; t < SZ; t++) {
            int mk = t % K2, r = t / K2, ml = r % L2, j = r / L2;
            uchar4 c;
            c.x = (unsigned char)a;
            c.y = (unsigned char)t;
            c.z = (unsigned char)(PB[a] + j * K2 + mk);
            c.w = (unsigned char)(LOFF2[l] + ml);
            g_ct[flat++] = c;
        }
    }
    for (; flat < 288; flat++) g_ct[flat] = make_uchar4(0, 0, 0, 0);
    int s = 0;
    for (int a = 0; a < 9; a++) {
        int k = a / 3, l = a % 3;
        int J = 2 * min(k, l) + 1, K2 = 2 * k + 1;
        int p = l * 3 + k;
        int quadbase = c_Roff4[p] / 4;
        for (int j = 0; j < J; j++)
            for (int mk = 0; mk < K2; mk++) {
                uchar4 c;
                c.x = (unsigned char)(quadbase + j);
                c.y = (unsigned char)(FOFF2[k] + mk);
                c.z = (unsigned char)(PB[a] + j * K2 + mk);
                c.w = 0;
                g_bt[s++] = c;
            }
    }
    for (; s < 96; s++) g_bt[s] = make_uchar4(0, 0, 0, 0);
}

// Per node: qi[2*m+o] = q[o, m] (m in [0,9)); fi[2*pos+i] = f-channel i at pos.
__global__ void k_node(const float* __restrict__ f0, const float* __restrict__ f1,
                       const float* __restrict__ f2, const float* __restrict__ wq, int N) {
    int n = blockIdx.x * blockDim.x + threadIdx.x;
    if (n >= N) return;
    const float* F0 = f0 + (size_t)n * 2;
    const float* F1 = f1 + (size_t)n * 6;
    const float* F2 = f2 + (size_t)n * 10;
    float* o_ = g_node + (size_t)n * 36;
#pragma unroll
    for (int o = 0; o < 2; o++) {
        o_[2 * 0 + o] = wq[0 + o * 2 + 0] * F0[0] + wq[0 + o * 2 + 1] * F0[1];
#pragma unroll
        for (int m = 0; m < 3; m++)
            o_[2 * (1 + m) + o] = wq[4 + o * 2 + 0] * F1[m] + wq[4 + o * 2 + 1] * F1[3 + m];
#pragma unroll
        for (int m = 0; m < 5; m++)
            o_[2 * (4 + m) + o] = wq[8 + o * 2 + 0] * F2[m] + wq[8 + o * 2 + 1] * F2[5 + m];
    }
    float* fo = o_ + 18;
#pragma unroll
    for (int i = 0; i < 2; i++) fo[2 * 0 + i] = F0[i];
#pragma unroll
    for (int m = 0; m < 3; m++)
#pragma unroll
        for (int i = 0; i < 2; i++) fo[2 * (1 + m) + i] = F1[i * 3 + m];
#pragma unroll
    for (int m = 0; m < 5; m++)
#pragma unroll
        for (int i = 0; i < 2; i++) fo[2 * (4 + m) + i] = F2[i * 5 + m];
}

__global__ void k_hist(const float* __restrict__ dist, int E) {
    __shared__ float h[3 * NB];
    for (int i = threadIdx.x; i < 3 * NB; i += blockDim.x) h[i] = 0.f;
    __syncthreads();
    int i = blockIdx.x * blockDim.x + threadIdx.x, st = gridDim.x * blockDim.x;
    for (int e = i; e < E; e += st) {
        float d = dist[e];
        int b = (int)(d * (float)NB);
        b = max(0, min(NB - 1, b));
        atomicAdd(&h[b], 1.f);
        atomicAdd(&h[NB + b], d);
        atomicAdd(&h[2 * NB + b], d * d);
    }
    __syncthreads();
    for (int j = threadIdx.x; j < 3 * NB; j += blockDim.x)
        if (h[j] != 0.f) atomicAdd(&g_hist[j], h[j]);
}

__global__ void k_distmv(const float* __restrict__ rW1, const float* __restrict__ rg1,
                         const float* __restrict__ rbb1, int E) {
    __shared__ double rc[256], r1[256], r2[256];
    __shared__ float smu, svar;
    int t = threadIdx.x;
    double c = 0, s1 = 0, s2 = 0;
    for (int b = t; b < NB; b += 256) {
        c  += (double)g_hist[b];
        s1 += (double)g_hist[NB + b];
        s2 += (double)g_hist[2 * NB + b];
    }
    rc[t] = c; r1[t] = s1; r2[t] = s2;
    __syncthreads();
    for (int o = 128; o > 0; o >>= 1) {
        if (t < o) { rc[t] += rc[t + o]; r1[t] += r1[t + o]; r2[t] += r2[t + o]; }
        __syncthreads();
    }
    if (t == 0) {
        double mu  = r1[0] / (double)E;
        double var = r2[0] / (double)E - mu * mu;
        if (var < 0) var = 0;
        smu = (float)mu; svar = (float)var;
    }
    __syncthreads();
    if (t < 90) {
        float w = rW1[t], gi = rg1[t];
        float inv = rsqrtf(svar * w * w + EPSV);
        g_AB[t]      = w * gi * inv;
        g_AB[90 + t] = rbb1[t] - w * smu * gi * inv;
    }
}

__global__ void k_stats(const float* __restrict__ rW2, const float* __restrict__ rb2) {
    __shared__ float sA[90], sB[90];
    int t = threadIdx.x;
    if (t < 90) { sA[t] = g_AB[t]; sB[t] = g_AB[90 + t]; }
    __syncthreads();
    if (t >= 270) return;
    int p = t / 30;
    double s1 = 0, s2 = 0;
    int b0 = blockIdx.x * 16;
    for (int bb = 0; bb < 16; bb++) {
        int b = b0 + bb;
        float cnt = g_hist[b];
        if (cnt == 0.f) continue;
        float m1 = g_hist[NB + b], m2 = g_hist[2 * NB + b];
        float dc = ((float)b + 0.5f) * (1.0f / (float)NB);
        float alpha = rb2[t], beta = 0.f;
#pragma unroll
        for (int u = 0; u < 10; u++) {
            float A = sA[p * 10 + u], Bv = sB[p * 10 + u];
            if (fmaf(A, dc, Bv) > 0.f) {
                float w = rW2[p * 300 + (t - p * 30) * 10 + u];
                alpha = fmaf(w, Bv, alpha);
                beta  = fmaf(w, A,  beta);
            }
        }
        double a = alpha, be = beta;
        s1 += a * (double)cnt + be * (double)m1;
        s2 += a * a * (double)cnt + 2.0 * a * be * (double)m1 + be * be * (double)m2;
    }
    atomicAdd(&g_stats[2 * t],     s1);
    atomicAdd(&g_stats[2 * t + 1], s2);
}

__global__ void k_bn2(const float* __restrict__ rg2, const float* __restrict__ rbb2, int E) {
    int t = threadIdx.x;
    if (t < 270) {
        double mean = g_stats[2 * t] / (double)E;
        double var  = g_stats[2 * t + 1] / (double)E - mean * mean;
        if (var < 0) var = 0;
        float sc = rg2[t] * rsqrtf((float)var + EPSV);
        g_bn2[t]       = sc;
        g_bn2[270 + t] = rbb2[t] - (float)mean * sc;
    }
}

// LUT rows. grid = NLUT+1, 288 threads. Writes own row into slot0 and into
// slot1 of the previous row (interleaved pairs for single-LDG.64 interp).
__global__ void k_lut(const float* __restrict__ rW2, const float* __restrict__ rb2,
                      const float* __restrict__ rW3, const float* __restrict__ rb3) {
    __shared__ float h1[90], h2[272];
    int t = threadIdx.x;
    float d = (float)blockIdx.x * (1.0f / (float)NLUT);
    if (t < 90) h1[t] = fmaxf(0.f, fmaf(g_AB[t], d, g_AB[90 + t]));
    __syncthreads();
    if (t < 270) {
        int p = t / 30;
        float z = rb2[t];
#pragma unroll
        for (int u = 0; u < 10; u++)
            z = fmaf(rW2[p * 300 + (t - p * 30) * 10 + u], h1[p * 10 + u], z);
        h2[t] = fmaxf(0.f, fmaf(z, g_bn2[t], g_bn2[270 + t]));
    }
    __syncthreads();
    if (t < 80) {
        float R = 0.f;
        if (t < 76) {
            int p = 0;
#pragma unroll
            for (int pp = 1; pp < 9; pp++) if (t >= c_Roff4[pp]) p = pp;
            int r = t - c_Roff4[p];
            R = rb3[p * 20 + r];
#pragma unroll
            for (int v = 0; v < 30; v++)
                R = fmaf(rW3[p * 600 + r * 30 + v], h2[p * 30 + v], R);
        }
        size_t b = blockIdx.x;
        g_lut2[(b * 80 + t) * 2] = R;
        if (b > 0) g_lut2[((b - 1) * 80 + t) * 2 + 1] = R;
    }
}

// -------- main kernel ------------------------------------------------------
// shared per warp (stride 256 floats): R[0..76) | qi[76..94) | fi[94..112) | B2[112..250)
__global__ void __launch_bounds__(256, 2) k_main(
    const int* __restrict__ dst, const float* __restrict__ dist,
    const float* __restrict__ wa0, const float* __restrict__ wa1,
    const float* __restrict__ wa2, const float* __restrict__ wa3,
    const float* __restrict__ wa4, const float* __restrict__ wa5,
    const float* __restrict__ wa6, const float* __restrict__ wa7,
    const float* __restrict__ wa8,
    float* __restrict__ eout, int E) {
    __shared__ __align__(16) float S[8 * 256];
    int lane = threadIdx.x & 31;
    float* sh  = S + ((threadIdx.x >> 5) << 8);
    float* shQ = sh + 76;
    float* shF = sh + 94;
    float* shB = sh + 112;

    const float* wb[9] = {wa0, wa1, wa2, wa3, wa4, wa5, wa6, wa7, wa8};

    // per-lane register tables
    const float* sp[9];
    int sstr[9], sb[9], sq[9];
#pragma unroll
    for (int it = 0; it < 9; it++) {
        uchar4 c = g_ct[it * 32 + lane];
        sp[it]   = wb[c.x] + c.y;
        sstr[it] = c_SZ[c.x];
        sb[it]   = (int)c.z * 2;
        sq[it]   = (int)c.w * 2;
    }
    int bquad[3], bfp[3], bpr[3];
#pragma unroll
    for (int it = 0; it < 3; it++) {
        uchar4 c = g_bt[it * 32 + lane];
        bquad[it] = (int)c.x * 4;
        bfp[it]   = (int)c.y * 2;
        bpr[it]   = (int)c.z * 2;
    }

    int gw = (int)((blockIdx.x * blockDim.x + threadIdx.x) >> 5);
    int nw = (int)((gridDim.x * blockDim.x) >> 5);

    for (int e = gw; e < E; e += nw) {
        int nd  = dst[e];
        float d = dist[e];

        const float* np = g_node + (size_t)nd * 36;
        shQ[lane] = np[lane];
        if (lane < 4) shQ[32 + lane] = np[32 + lane];

        float td = d * (float)NLUT;
        int i0 = (int)td;
        i0 = max(0, min(NLUT - 1, i0));
        float fr = td - (float)i0;
        const float2* Lp = (const float2*)g_lut2 + (size_t)i0 * 80;
#pragma unroll
        for (int it = 0; it < 3; it++) {
            int i = it * 32 + lane;
            if (it < 2 || lane < 12) {
                float2 rr = Lp[i];
                sh[i] = fmaf(fr, rr.y - rr.x, rr.x);
            }
        }
        __syncwarp();

        // B build: b[o] = sum_i R[j,o,i] * f[i, pos]
#pragma unroll
        for (int it = 0; it < 3; it++) {
            if (it < 2 || lane < 5) {
                float4 R4 = *(const float4*)(sh + bquad[it]);
                float2 fp = *(const float2*)(shF + bfp[it]);
                float b0 = R4.x * fp.x + R4.y * fp.y;
                float b1 = R4.z * fp.x + R4.w * fp.y;
                *(float2*)(shB + bpr[it]) = make_float2(b0, b1);
            }
        }
        __syncwarp();

        float acc = 0.f;
#pragma unroll
        for (int it = 0; it < 9; it++) {
            if (it < 8 || lane < 3) {   // 259 = 8*32 + 3
                float w  = sp[it][(size_t)e * sstr[it]];
                float2 b = *(const float2*)(shB + sb[it]);
                float2 q = *(const float2*)(shQ + sq[it]);
                acc = fmaf(w, fmaf(q.x, b.x, q.y * b.y), acc);
            }
        }
#pragma unroll
        for (int o = 16; o > 0; o >>= 1)
            acc += __shfl_xor_sync(0xFFFFFFFFu, acc, o);

        if (lane == 0) {
            float ev = expf(acc);
            eout[e] = ev;
            atomicAdd(&g_s[nd], ev);
        }
        __syncwarp();
    }
}

__global__ void k_div(const int* __restrict__ dst, float* __restrict__ out, int E) {
    int e = blockIdx.x * blockDim.x + threadIdx.x;
    if (e < E) out[e] = out[e] / g_s[dst[e]];
}

// ---------------------------------------------------------------------------
extern "C" void kernel_launch(void* const* d_in, const int* in_sizes, int n_in,
                              void* d_out, int out_size) {
    int b = (n_in == 26) ? 1 : 0;
    const int*   dst  = (const int*)d_in[b + 0];
    const float* dist = (const float*)d_in[b + 1];
    const float* f0   = (const float*)d_in[b + 2];
    const float* f1   = (const float*)d_in[b + 3];
    const float* f2   = (const float*)d_in[b + 4];
    const float* wq   = (const float*)d_in[b + 5];
    const float* wj[9];
    for (int i = 0; i < 9; i++) wj[i] = (const float*)d_in[b + 6 + i];  // a = k*3+l
    const float* rW1  = (const float*)d_in[b + 15];
    const float* rg1  = (const float*)d_in[b + 17];
    const float* rbb1 = (const float*)d_in[b + 18];
    const float* rW2  = (const float*)d_in[b + 19];
    const float* rb2  = (const float*)d_in[b + 20];
    const float* rg2  = (const float*)d_in[b + 21];
    const float* rbb2 = (const float*)d_in[b + 22];
    const float* rW3  = (const float*)d_in[b + 23];
    const float* rb3  = (const float*)d_in[b + 24];

    int E = in_sizes[b + 0];
    int N = in_sizes[b + 2] / 2;
    float* out = (float*)d_out;

    k_zero<<<256, 256>>>();
    k_tables<<<1, 32>>>();
    k_node<<<(N + 255) / 256, 256>>>(f0, f1, f2, wq, N);
    k_hist<<<1024, 256>>>(dist, E);
    k_distmv<<<1, 256>>>(rW1, rg1, rbb1, E);
    k_stats<<<NB / 16, 288>>>(rW2, rb2);
    k_bn2<<<1, 288>>>(rg2, rbb2, E);
    k_lut<<<NLUT + 1, 288>>>(rW2, rb2, rW3, rb3);
    k_main<<<296, 256>>>(dst, dist,
                         wj[0], wj[1], wj[2],
                         wj[3], wj[4], wj[5],
                         wj[6], wj[7], wj[8],
                         out, E);
    k_div<<<(E + 255) / 256, 256>>>(dst, out, E);
}

// round 5
// speedup vs baseline: 2.9087x; 1.5558x over previous
#include <cuda_runtime.h>
#include <math.h>
#include <stdint.h>

// ============================================================================
// AttnBlock: SE(3)-attention edge softmax, D=2, C=2.
//  - radial MLP = scalar piecewise-linear function of dist -> 4096-pt LUT
//    (layer1 BN analytic, layer2 BN via exact per-bin moment histogram).
//  - main kernel: warp per 2 edges (software pipelined), register-resident
//    per-lane index tables + pointer stepping, vectorized LDS.
// ============================================================================

#define NB     2048
#define NLUT   4096
#define NMAX   50048
#define EPSV   1e-5f

__device__ float  g_hist[3 * NB];
__device__ float  g_AB[180];
__device__ double g_stats[540];
__device__ float  g_bn2[540];
__device__ float  g_lut2[(size_t)(NLUT + 1) * 160];  // [i0][i<80][{row i0, row i0+1}]
__device__ float  g_node[(size_t)NMAX * 36];         // qi[18] | fi[18] interleaved pairs
__device__ float  g_s[NMAX];
__device__ uchar4 g_ct[288];   // contraction slot -> (arr, off, b2pair, qpair)
__device__ uchar4 g_bt[96];    // B-build slot -> (Rquad, fpos, b2pair, 0)

__constant__ int c_Roff4[9] = {0, 4, 8, 12, 16, 28, 40, 44, 56}; // p = l*3+k
__constant__ int c_SZ[9]    = {1, 3, 5, 3, 27, 45, 5, 45, 125};  // a = k*3+l

// ---------------------------------------------------------------------------
__global__ void k_zero() {
    int i = blockIdx.x * blockDim.x + threadIdx.x;
    int st = gridDim.x * blockDim.x;
    for (int t = i; t < NMAX; t += st)   g_s[t] = 0.f;
    for (int t = i; t < 3 * NB; t += st) g_hist[t] = 0.f;
    for (int t = i; t < 540; t += st)    g_stats[t] = 0.0;
}

__global__ void k_tables() {
    if (threadIdx.x || blockIdx.x) return;
    const int LOFF2[3] = {0, 1, 4};
    const int FOFF2[3] = {0, 1, 4};
    int PB[9]; int pb = 0;
    for (int a = 0; a < 9; a++) {
        int k = a / 3, l = a % 3;
        int J = 2 * min(k, l) + 1, K2 = 2 * k + 1;
        PB[a] = pb; pb += J * K2;
    }
    int flat = 0;
    for (int a = 0; a < 9; a++) {
        int k = a / 3, l = a % 3;
        int J = 2 * min(k, l) + 1, K2 = 2 * k + 1, L2 = 2 * l + 1;
        int SZ = J * L2 * K2;
        for (int t = 0; t < SZ; t++) {
            int mk = t % K2, r = t / K2, ml = r % L2, j = r / L2;
            uchar4 c;
            c.x = (unsigned char)a;
            c.y = (unsigned char)t;
            c.z = (unsigned char)(PB[a] + j * K2 + mk);
            c.w = (unsigned char)(LOFF2[l] + ml);
            g_ct[flat++] = c;
        }
    }
    for (; flat < 288; flat++) g_ct[flat] = make_uchar4(0, 0, 0, 0);
    int s = 0;
    for (int a = 0; a < 9; a++) {
        int k = a / 3, l = a % 3;
        int J = 2 * min(k, l) + 1, K2 = 2 * k + 1;
        int p = l * 3 + k;
        int quadbase = c_Roff4[p] / 4;
        for (int j = 0; j < J; j++)
            for (int mk = 0; mk < K2; mk++) {
                uchar4 c;
                c.x = (unsigned char)(quadbase + j);
                c.y = (unsigned char)(FOFF2[k] + mk);
                c.z = (unsigned char)(PB[a] + j * K2 + mk);
                c.w = 0;
                g_bt[s++] = c;
            }
    }
    for (; s < 96; s++) g_bt[s] = make_uchar4(0, 0, 0, 0);
}

// Per node: qi[2*m+o] = q[o,m]; fi[2*pos+i] = f-channel i at pos.
__global__ void k_node(const float* __restrict__ f0, const float* __restrict__ f1,
                       const float* __restrict__ f2, const float* __restrict__ wq, int N) {
    int n = blockIdx.x * blockDim.x + threadIdx.x;
    if (n >= N) return;
    const float* F0 = f0 + (size_t)n * 2;
    const float* F1 = f1 + (size_t)n * 6;
    const float* F2 = f2 + (size_t)n * 10;
    float* o_ = g_node + (size_t)n * 36;
#pragma unroll
    for (int o = 0; o < 2; o++) {
        o_[2 * 0 + o] = wq[0 + o * 2 + 0] * F0[0] + wq[0 + o * 2 + 1] * F0[1];
#pragma unroll
        for (int m = 0; m < 3; m++)
            o_[2 * (1 + m) + o] = wq[4 + o * 2 + 0] * F1[m] + wq[4 + o * 2 + 1] * F1[3 + m];
#pragma unroll
        for (int m = 0; m < 5; m++)
            o_[2 * (4 + m) + o] = wq[8 + o * 2 + 0] * F2[m] + wq[8 + o * 2 + 1] * F2[5 + m];
    }
    float* fo = o_ + 18;
#pragma unroll
    for (int i = 0; i < 2; i++) fo[2 * 0 + i] = F0[i];
#pragma unroll
    for (int m = 0; m < 3; m++)
#pragma unroll
        for (int i = 0; i < 2; i++) fo[2 * (1 + m) + i] = F1[i * 3 + m];
#pragma unroll
    for (int m = 0; m < 5; m++)
#pragma unroll
        for (int i = 0; i < 2; i++) fo[2 * (4 + m) + i] = F2[i * 5 + m];
}

__global__ void k_hist(const float* __restrict__ dist, int E) {
    __shared__ float h[3 * NB];
    for (int i = threadIdx.x; i < 3 * NB; i += blockDim.x) h[i] = 0.f;
    __syncthreads();
    int i = blockIdx.x * blockDim.x + threadIdx.x, st = gridDim.x * blockDim.x;
    for (int e = i; e < E; e += st) {
        float d = dist[e];
        int b = (int)(d * (float)NB);
        b = max(0, min(NB - 1, b));
        atomicAdd(&h[b], 1.f);
        atomicAdd(&h[NB + b], d);
        atomicAdd(&h[2 * NB + b], d * d);
    }
    __syncthreads();
    for (int j = threadIdx.x; j < 3 * NB; j += blockDim.x)
        if (h[j] != 0.f) atomicAdd(&g_hist[j], h[j]);
}

__global__ void k_distmv(const float* __restrict__ rW1, const float* __restrict__ rg1,
                         const float* __restrict__ rbb1, int E) {
    __shared__ double rc[256], r1[256], r2[256];
    __shared__ float smu, svar;
    int t = threadIdx.x;
    double c = 0, s1 = 0, s2 = 0;
    for (int b = t; b < NB; b += 256) {
        c  += (double)g_hist[b];
        s1 += (double)g_hist[NB + b];
        s2 += (double)g_hist[2 * NB + b];
    }
    rc[t] = c; r1[t] = s1; r2[t] = s2;
    __syncthreads();
    for (int o = 128; o > 0; o >>= 1) {
        if (t < o) { rc[t] += rc[t + o]; r1[t] += r1[t + o]; r2[t] += r2[t + o]; }
        __syncthreads();
    }
    if (t == 0) {
        double mu  = r1[0] / (double)E;
        double var = r2[0] / (double)E - mu * mu;
        if (var < 0) var = 0;
        smu = (float)mu; svar = (float)var;
    }
    __syncthreads();
    if (t < 90) {
        float w = rW1[t], gi = rg1[t];
        float inv = rsqrtf(svar * w * w + EPSV);
        g_AB[t]      = w * gi * inv;
        g_AB[90 + t] = rbb1[t] - w * smu * gi * inv;
    }
}

__global__ void k_stats(const float* __restrict__ rW2, const float* __restrict__ rb2) {
    __shared__ float sA[90], sB[90];
    int t = threadIdx.x;
    if (t < 90) { sA[t] = g_AB[t]; sB[t] = g_AB[90 + t]; }
    __syncthreads();
    if (t >= 270) return;
    int p = t / 30;
    double s1 = 0, s2 = 0;
    int b0 = blockIdx.x * 16;
    for (int bb = 0; bb < 16; bb++) {
        int b = b0 + bb;
        float cnt = g_hist[b];
        if (cnt == 0.f) continue;
        float m1 = g_hist[NB + b], m2 = g_hist[2 * NB + b];
        float dc = ((float)b + 0.5f) * (1.0f / (float)NB);
        float alpha = rb2[t], beta = 0.f;
#pragma unroll
        for (int u = 0; u < 10; u++) {
            float A = sA[p * 10 + u], Bv = sB[p * 10 + u];
            if (fmaf(A, dc, Bv) > 0.f) {
                float w = rW2[p * 300 + (t - p * 30) * 10 + u];
                alpha = fmaf(w, Bv, alpha);
                beta  = fmaf(w, A,  beta);
            }
        }
        double a = alpha, be = beta;
        s1 += a * (double)cnt + be * (double)m1;
        s2 += a * a * (double)cnt + 2.0 * a * be * (double)m1 + be * be * (double)m2;
    }
    atomicAdd(&g_stats[2 * t],     s1);
    atomicAdd(&g_stats[2 * t + 1], s2);
}

__global__ void k_bn2(const float* __restrict__ rg2, const float* __restrict__ rbb2, int E) {
    int t = threadIdx.x;
    if (t < 270) {
        double mean = g_stats[2 * t] / (double)E;
        double var  = g_stats[2 * t + 1] / (double)E - mean * mean;
        if (var < 0) var = 0;
        float sc = rg2[t] * rsqrtf((float)var + EPSV);
        g_bn2[t]       = sc;
        g_bn2[270 + t] = rbb2[t] - (float)mean * sc;
    }
}

// LUT rows: eval radial at NLUT+1 points; interleaved (row i, row i+1) pairs.
__global__ void k_lut(const float* __restrict__ rW2, const float* __restrict__ rb2,
                      const float* __restrict__ rW3, const float* __restrict__ rb3) {
    __shared__ float h1[90], h2[272];
    int t = threadIdx.x;
    float d = (float)blockIdx.x * (1.0f / (float)NLUT);
    if (t < 90) h1[t] = fmaxf(0.f, fmaf(g_AB[t], d, g_AB[90 + t]));
    __syncthreads();
    if (t < 270) {
        int p = t / 30;
        float z = rb2[t];
#pragma unroll
        for (int u = 0; u < 10; u++)
            z = fmaf(rW2[p * 300 + (t - p * 30) * 10 + u], h1[p * 10 + u], z);
        h2[t] = fmaxf(0.f, fmaf(z, g_bn2[t], g_bn2[270 + t]));
    }
    __syncthreads();
    if (t < 80) {
        float R = 0.f;
        if (t < 76) {
            int p = 0;
#pragma unroll
            for (int pp = 1; pp < 9; pp++) if (t >= c_Roff4[pp]) p = pp;
            int r = t - c_Roff4[p];
            R = rb3[p * 20 + r];
#pragma unroll
            for (int v = 0; v < 30; v++)
                R = fmaf(rW3[p * 600 + r * 30 + v], h2[p * 30 + v], R);
        }
        size_t b = blockIdx.x;
        g_lut2[(b * 80 + t) * 2] = R;
        if (b > 0) g_lut2[((b - 1) * 80 + t) * 2 + 1] = R;
    }
}

// -------- main kernel: warp per 2 edges ------------------------------------
// per-warp smem (512 floats): two buffers of 256:
//   buf: R[0..76) | qi[76..94) | fi[94..112) | B2[112..250)
__global__ void __launch_bounds__(256, 2) k_main(
    const int* __restrict__ dst, const float* __restrict__ dist,
    const float* __restrict__ wa0, const float* __restrict__ wa1,
    const float* __restrict__ wa2, const float* __restrict__ wa3,
    const float* __restrict__ wa4, const float* __restrict__ wa5,
    const float* __restrict__ wa6, const float* __restrict__ wa7,
    const float* __restrict__ wa8,
    float* __restrict__ eout, int E) {
    __shared__ __align__(16) float S[8 * 512];
    int lane = threadIdx.x & 31;
    float* s0 = S + ((threadIdx.x >> 5) << 9);
    float* s1 = s0 + 256;

    const float* wb[9] = {wa0, wa1, wa2, wa3, wa4, wa5, wa6, wa7, wa8};

    int gw = (int)((blockIdx.x * blockDim.x + threadIdx.x) >> 5);
    int nw = (int)((gridDim.x * blockDim.x) >> 5);

    // per-lane register tables (pointer-stepping form)
    const float* sp[9];
    int sstr[9], sstep[9], sb_[9], sq_[9];
#pragma unroll
    for (int it = 0; it < 9; it++) {
        uchar4 c = g_ct[it * 32 + lane];
        int sz   = c_SZ[c.x];
        sp[it]   = wb[c.x] + (int)c.y + 2 * gw * sz;
        sstr[it] = sz;
        sstep[it] = 2 * nw * sz;
        sb_[it]  = (int)c.z * 2;
        sq_[it]  = (int)c.w * 2;
    }
    int bquad[3], bfp[3], bpr[3];
#pragma unroll
    for (int it = 0; it < 3; it++) {
        uchar4 c = g_bt[it * 32 + lane];
        bquad[it] = (int)c.x * 4;
        bfp[it]   = (int)c.y * 2;
        bpr[it]   = (int)c.z * 2;
    }

    for (int e0 = 2 * gw; e0 < E; e0 += 2 * nw) {
        int e1 = e0 + 1;
        bool v1 = (e1 < E);

        int   nd0 = dst[e0];
        float d0  = dist[e0];
        int   nd1 = v1 ? dst[e1] : nd0;
        float d1  = v1 ? dist[e1] : d0;

        // node tables -> smem (both edges)
        const float* np0 = g_node + (size_t)nd0 * 36;
        const float* np1 = g_node + (size_t)nd1 * 36;
        s0[76 + lane] = np0[lane];
        s1[76 + lane] = np1[lane];
        if (lane < 4) {
            s0[108 + lane] = np0[32 + lane];
            s1[108 + lane] = np1[32 + lane];
        }

        // LUT interp (both edges)
        float td0 = d0 * (float)NLUT;
        int i00 = max(0, min(NLUT - 1, (int)td0));
        float fr0 = td0 - (float)i00;
        float td1 = d1 * (float)NLUT;
        int i01 = max(0, min(NLUT - 1, (int)td1));
        float fr1 = td1 - (float)i01;
        const float2* Lp0 = (const float2*)g_lut2 + (size_t)i00 * 80;
        const float2* Lp1 = (const float2*)g_lut2 + (size_t)i01 * 80;
#pragma unroll
        for (int it = 0; it < 3; it++) {
            int i = it * 32 + lane;
            if (it < 2 || lane < 12) {
                float2 ra = Lp0[i];
                float2 rb2_ = Lp1[i];
                s0[i] = fmaf(fr0, ra.y - ra.x, ra.x);
                s1[i] = fmaf(fr1, rb2_.y - rb2_.x, rb2_.x);
            }
        }
        __syncwarp();

        // B build (both edges)
#pragma unroll
        for (int it = 0; it < 3; it++) {
            if (it < 2 || lane < 5) {
                float4 Ra = *(const float4*)(s0 + bquad[it]);
                float2 fa = *(const float2*)(s0 + 94 + bfp[it]);
                *(float2*)(s0 + 112 + bpr[it]) =
                    make_float2(Ra.x * fa.x + Ra.y * fa.y, Ra.z * fa.x + Ra.w * fa.y);
                float4 Rb = *(const float4*)(s1 + bquad[it]);
                float2 fb = *(const float2*)(s1 + 94 + bfp[it]);
                *(float2*)(s1 + 112 + bpr[it]) =
                    make_float2(Rb.x * fb.x + Rb.y * fb.y, Rb.z * fb.x + Rb.w * fb.y);
            }
        }
        __syncwarp();

        // issue all wj loads for both edges up front (streaming)
        float w0[9], w1[9];
#pragma unroll
        for (int it = 0; it < 9; it++) {
            float a = __ldcs(sp[it]);                  // always in-bounds
            float b = v1 ? __ldcs(sp[it] + sstr[it]) : 0.f;
            bool valid = (it < 8) || (lane < 3);       // 259 = 8*32+3
            w0[it] = valid ? a : 0.f;
            w1[it] = valid ? b : 0.f;
        }

        float acc0 = 0.f, acc1 = 0.f;
#pragma unroll
        for (int it = 0; it < 9; it++) {
            float2 b0 = *(const float2*)(s0 + 112 + sb_[it]);
            float2 q0 = *(const float2*)(s0 + 76 + sq_[it]);
            acc0 = fmaf(w0[it], fmaf(q0.x, b0.x, q0.y * b0.y), acc0);
            float2 b1 = *(const float2*)(s1 + 112 + sb_[it]);
            float2 q1 = *(const float2*)(s1 + 76 + sq_[it]);
            acc1 = fmaf(w1[it], fmaf(q1.x, b1.x, q1.y * b1.y), acc1);
        }
#pragma unroll
        for (int o = 16; o > 0; o >>= 1) {
            acc0 += __shfl_xor_sync(0xFFFFFFFFu, acc0, o);
            acc1 += __shfl_xor_sync(0xFFFFFFFFu, acc1, o);
        }

        if (lane == 0) {
            float ev0 = expf(acc0);
            eout[e0] = ev0;
            atomicAdd(&g_s[nd0], ev0);
            if (v1) {
                float ev1 = expf(acc1);
                eout[e1] = ev1;
                atomicAdd(&g_s[nd1], ev1);
            }
        }
#pragma unroll
        for (int it = 0; it < 9; it++) sp[it] += sstep[it];
        __syncwarp();
    }
}

__global__ void k_div(const int* __restrict__ dst, float* __restrict__ out, int E) {
    int e = blockIdx.x * blockDim.x + threadIdx.x;
    if (e < E) out[e] = out[e] / g_s[dst[e]];
}

// ---------------------------------------------------------------------------
extern "C" void kernel_launch(void* const* d_in, const int* in_sizes, int n_in,
                              void* d_out, int out_size) {
    int b = (n_in == 26) ? 1 : 0;
    const int*   dst  = (const int*)d_in[b + 0];
    const float* dist = (const float*)d_in[b + 1];
    const float* f0   = (const float*)d_in[b + 2];
    const float* f1   = (const float*)d_in[b + 3];
    const float* f2   = (const float*)d_in[b + 4];
    const float* wq   = (const float*)d_in[b + 5];
    const float* wj[9];
    for (int i = 0; i < 9; i++) wj[i] = (const float*)d_in[b + 6 + i];  // a = k*3+l
    const float* rW1  = (const float*)d_in[b + 15];
    const float* rg1  = (const float*)d_in[b + 17];
    const float* rbb1 = (const float*)d_in[b + 18];
    const float* rW2  = (const float*)d_in[b + 19];
    const float* rb2  = (const float*)d_in[b + 20];
    const float* rg2  = (const float*)d_in[b + 21];
    const float* rbb2 = (const float*)d_in[b + 22];
    const float* rW3  = (const float*)d_in[b + 23];
    const float* rb3  = (const float*)d_in[b + 24];

    int E = in_sizes[b + 0];
    int N = in_sizes[b + 2] / 2;
    float* out = (float*)d_out;

    k_zero<<<256, 256>>>();
    k_tables<<<1, 32>>>();
    k_node<<<(N + 255) / 256, 256>>>(f0, f1, f2, wq, N);
    k_hist<<<1024, 256>>>(dist, E);
    k_distmv<<<1, 256>>>(rW1, rg1, rbb1, E);
    k_stats<<<NB / 16, 288>>>(rW2, rb2);
    k_bn2<<<1, 288>>>(rg2, rbb2, E);
    k_lut<<<NLUT + 1, 288>>>(rW2, rb2, rW3, rb3);
    k_main<<<296, 256>>>(dst, dist,
                         wj[0], wj[1], wj[2],
                         wj[3], wj[4], wj[5],
                         wj[6], wj[7], wj[8],
                         out, E);
    k_div<<<(E + 255) / 256, 256>>>(dst, out, E);
}

// round 6
// speedup vs baseline: 3.0484x; 1.0480x over previous
#include <cuda_runtime.h>
#include <math.h>
#include <stdint.h>

// ============================================================================
// AttnBlock: SE(3)-attention edge softmax, D=2, C=2.
//  - radial MLP = scalar piecewise-linear function of dist -> 2048-pt LUT
//    (layer1 BN analytic, layer2 BN via exact per-bin moment histogram).
//  - main kernel: warp per 2 edges, cross-iteration software pipeline:
//    wj loads issued first (addresses independent of dst/dist), next-iter
//    dst/dist prefetched, node/LUT+B-build overlap the wj DRAM latency.
// ============================================================================

#define NB     2048
#define NLUT   2048
#define NMAX   50048
#define EPSV   1e-5f

__device__ float  g_hist[3 * NB];
__device__ float  g_AB[180];
__device__ double g_stats[540];
__device__ float  g_bn2[540];
__device__ float  g_lut2[(size_t)(NLUT + 1) * 160];  // [i0][i<80][{row i0, row i0+1}]
__device__ float  g_node[(size_t)NMAX * 36];         // qi[18] | fi[18] interleaved pairs
__device__ float  g_s[NMAX];
__device__ uchar4 g_ct[288];   // contraction slot -> (arr, off, b2pair, qpair)
__device__ uchar4 g_bt[96];    // B-build slot -> (Rquad, fpos, b2pair, 0)

__constant__ int c_Roff4[9] = {0, 4, 8, 12, 16, 28, 40, 44, 56}; // p = l*3+k
__constant__ int c_SZ[9]    = {1, 3, 5, 3, 27, 45, 5, 45, 125};  // a = k*3+l

// ---------------------------------------------------------------------------
__global__ void k_zero() {
    int i = blockIdx.x * blockDim.x + threadIdx.x;
    int st = gridDim.x * blockDim.x;
    for (int t = i; t < NMAX; t += st)   g_s[t] = 0.f;
    for (int t = i; t < 3 * NB; t += st) g_hist[t] = 0.f;
    for (int t = i; t < 540; t += st)    g_stats[t] = 0.0;
}

__global__ void k_tables() {
    if (threadIdx.x || blockIdx.x) return;
    const int LOFF2[3] = {0, 1, 4};
    const int FOFF2[3] = {0, 1, 4};
    int PB[9]; int pb = 0;
    for (int a = 0; a < 9; a++) {
        int k = a / 3, l = a % 3;
        int J = 2 * min(k, l) + 1, K2 = 2 * k + 1;
        PB[a] = pb; pb += J * K2;
    }
    int flat = 0;
    for (int a = 0; a < 9; a++) {
        int k = a / 3, l = a % 3;
        int J = 2 * min(k, l) + 1, K2 = 2 * k + 1, L2 = 2 * l + 1;
        int SZ = J * L2 * K2;
        for (int t = 0; t < SZ; t++) {
            int mk = t % K2, r = t / K2, ml = r % L2, j = r / L2;
            uchar4 c;
            c.x = (unsigned char)a;
            c.y = (unsigned char)t;
            c.z = (unsigned char)(PB[a] + j * K2 + mk);
            c.w = (unsigned char)(LOFF2[l] + ml);
            g_ct[flat++] = c;
        }
    }
    for (; flat < 288; flat++) g_ct[flat] = make_uchar4(0, 0, 0, 0);
    int s = 0;
    for (int a = 0; a < 9; a++) {
        int k = a / 3, l = a % 3;
        int J = 2 * min(k, l) + 1, K2 = 2 * k + 1;
        int p = l * 3 + k;
        int quadbase = c_Roff4[p] / 4;
        for (int j = 0; j < J; j++)
            for (int mk = 0; mk < K2; mk++) {
                uchar4 c;
                c.x = (unsigned char)(quadbase + j);
                c.y = (unsigned char)(FOFF2[k] + mk);
                c.z = (unsigned char)(PB[a] + j * K2 + mk);
                c.w = 0;
                g_bt[s++] = c;
            }
    }
    for (; s < 96; s++) g_bt[s] = make_uchar4(0, 0, 0, 0);
}

// Per node: qi[2*m+o] = q[o,m]; fi[2*pos+i] = f-channel i at pos.
__global__ void k_node(const float* __restrict__ f0, const float* __restrict__ f1,
                       const float* __restrict__ f2, const float* __restrict__ wq, int N) {
    int n = blockIdx.x * blockDim.x + threadIdx.x;
    if (n >= N) return;
    const float* F0 = f0 + (size_t)n * 2;
    const float* F1 = f1 + (size_t)n * 6;
    const float* F2 = f2 + (size_t)n * 10;
    float* o_ = g_node + (size_t)n * 36;
#pragma unroll
    for (int o = 0; o < 2; o++) {
        o_[2 * 0 + o] = wq[0 + o * 2 + 0] * F0[0] + wq[0 + o * 2 + 1] * F0[1];
#pragma unroll
        for (int m = 0; m < 3; m++)
            o_[2 * (1 + m) + o] = wq[4 + o * 2 + 0] * F1[m] + wq[4 + o * 2 + 1] * F1[3 + m];
#pragma unroll
        for (int m = 0; m < 5; m++)
            o_[2 * (4 + m) + o] = wq[8 + o * 2 + 0] * F2[m] + wq[8 + o * 2 + 1] * F2[5 + m];
    }
    float* fo = o_ + 18;
#pragma unroll
    for (int i = 0; i < 2; i++) fo[2 * 0 + i] = F0[i];
#pragma unroll
    for (int m = 0; m < 3; m++)
#pragma unroll
        for (int i = 0; i < 2; i++) fo[2 * (1 + m) + i] = F1[i * 3 + m];
#pragma unroll
    for (int m = 0; m < 5; m++)
#pragma unroll
        for (int i = 0; i < 2; i++) fo[2 * (4 + m) + i] = F2[i * 5 + m];
}

__global__ void k_hist(const float* __restrict__ dist, int E) {
    __shared__ float h[3 * NB];
    for (int i = threadIdx.x; i < 3 * NB; i += blockDim.x) h[i] = 0.f;
    __syncthreads();
    int i = blockIdx.x * blockDim.x + threadIdx.x, st = gridDim.x * blockDim.x;
    for (int e = i; e < E; e += st) {
        float d = dist[e];
        int b = (int)(d * (float)NB);
        b = max(0, min(NB - 1, b));
        atomicAdd(&h[b], 1.f);
        atomicAdd(&h[NB + b], d);
        atomicAdd(&h[2 * NB + b], d * d);
    }
    __syncthreads();
    for (int j = threadIdx.x; j < 3 * NB; j += blockDim.x)
        if (h[j] != 0.f) atomicAdd(&g_hist[j], h[j]);
}

__global__ void k_distmv(const float* __restrict__ rW1, const float* __restrict__ rg1,
                         const float* __restrict__ rbb1, int E) {
    __shared__ double rc[256], r1[256], r2[256];
    __shared__ float smu, svar;
    int t = threadIdx.x;
    double c = 0, s1 = 0, s2 = 0;
    for (int b = t; b < NB; b += 256) {
        c  += (double)g_hist[b];
        s1 += (double)g_hist[NB + b];
        s2 += (double)g_hist[2 * NB + b];
    }
    rc[t] = c; r1[t] = s1; r2[t] = s2;
    __syncthreads();
    for (int o = 128; o > 0; o >>= 1) {
        if (t < o) { rc[t] += rc[t + o]; r1[t] += r1[t + o]; r2[t] += r2[t + o]; }
        __syncthreads();
    }
    if (t == 0) {
        double mu  = r1[0] / (double)E;
        double var = r2[0] / (double)E - mu * mu;
        if (var < 0) var = 0;
        smu = (float)mu; svar = (float)var;
    }
    __syncthreads();
    if (t < 90) {
        float w = rW1[t], gi = rg1[t];
        float inv = rsqrtf(svar * w * w + EPSV);
        g_AB[t]      = w * gi * inv;
        g_AB[90 + t] = rbb1[t] - w * smu * gi * inv;
    }
}

__global__ void k_stats(const float* __restrict__ rW2, const float* __restrict__ rb2) {
    __shared__ float sA[90], sB[90];
    int t = threadIdx.x;
    if (t < 90) { sA[t] = g_AB[t]; sB[t] = g_AB[90 + t]; }
    __syncthreads();
    if (t >= 270) return;
    int p = t / 30;
    double s1 = 0, s2 = 0;
    int b0 = blockIdx.x * 16;
    for (int bb = 0; bb < 16; bb++) {
        int b = b0 + bb;
        float cnt = g_hist[b];
        if (cnt == 0.f) continue;
        float m1 = g_hist[NB + b], m2 = g_hist[2 * NB + b];
        float dc = ((float)b + 0.5f) * (1.0f / (float)NB);
        float alpha = rb2[t], beta = 0.f;
#pragma unroll
        for (int u = 0; u < 10; u++) {
            float A = sA[p * 10 + u], Bv = sB[p * 10 + u];
            if (fmaf(A, dc, Bv) > 0.f) {
                float w = rW2[p * 300 + (t - p * 30) * 10 + u];
                alpha = fmaf(w, Bv, alpha);
                beta  = fmaf(w, A,  beta);
            }
        }
        double a = alpha, be = beta;
        s1 += a * (double)cnt + be * (double)m1;
        s2 += a * a * (double)cnt + 2.0 * a * be * (double)m1 + be * be * (double)m2;
    }
    atomicAdd(&g_stats[2 * t],     s1);
    atomicAdd(&g_stats[2 * t + 1], s2);
}

__global__ void k_bn2(const float* __restrict__ rg2, const float* __restrict__ rbb2, int E) {
    int t = threadIdx.x;
    if (t < 270) {
        double mean = g_stats[2 * t] / (double)E;
        double var  = g_stats[2 * t + 1] / (double)E - mean * mean;
        if (var < 0) var = 0;
        float sc = rg2[t] * rsqrtf((float)var + EPSV);
        g_bn2[t]       = sc;
        g_bn2[270 + t] = rbb2[t] - (float)mean * sc;
    }
}

// LUT rows: eval radial at NLUT+1 points; interleaved (row i, row i+1) pairs.
__global__ void k_lut(const float* __restrict__ rW2, const float* __restrict__ rb2,
                      const float* __restrict__ rW3, const float* __restrict__ rb3) {
    __shared__ float h1[90], h2[272];
    int t = threadIdx.x;
    float d = (float)blockIdx.x * (1.0f / (float)NLUT);
    if (t < 90) h1[t] = fmaxf(0.f, fmaf(g_AB[t], d, g_AB[90 + t]));
    __syncthreads();
    if (t < 270) {
        int p = t / 30;
        float z = rb2[t];
#pragma unroll
        for (int u = 0; u < 10; u++)
            z = fmaf(rW2[p * 300 + (t - p * 30) * 10 + u], h1[p * 10 + u], z);
        h2[t] = fmaxf(0.f, fmaf(z, g_bn2[t], g_bn2[270 + t]));
    }
    __syncthreads();
    if (t < 80) {
        float R = 0.f;
        if (t < 76) {
            int p = 0;
#pragma unroll
            for (int pp = 1; pp < 9; pp++) if (t >= c_Roff4[pp]) p = pp;
            int r = t - c_Roff4[p];
            R = rb3[p * 20 + r];
#pragma unroll
            for (int v = 0; v < 30; v++)
                R = fmaf(rW3[p * 600 + r * 30 + v], h2[p * 30 + v], R);
        }
        size_t b = blockIdx.x;
        g_lut2[(b * 80 + t) * 2] = R;
        if (b > 0) g_lut2[((b - 1) * 80 + t) * 2 + 1] = R;
    }
}

// -------- main kernel: warp per 2 edges, software pipelined ----------------
__global__ void __launch_bounds__(256, 2) k_main(
    const int* __restrict__ dst, const float* __restrict__ dist,
    const float* __restrict__ wa0, const float* __restrict__ wa1,
    const float* __restrict__ wa2, const float* __restrict__ wa3,
    const float* __restrict__ wa4, const float* __restrict__ wa5,
    const float* __restrict__ wa6, const float* __restrict__ wa7,
    const float* __restrict__ wa8,
    float* __restrict__ eout, int E) {
    __shared__ __align__(16) float S[8 * 512];
    int lane = threadIdx.x & 31;
    float* s0 = S + ((threadIdx.x >> 5) << 9);
    float* s1 = s0 + 256;

    const float* wb[9] = {wa0, wa1, wa2, wa3, wa4, wa5, wa6, wa7, wa8};

    int gw = (int)((blockIdx.x * blockDim.x + threadIdx.x) >> 5);
    int nw = (int)((gridDim.x * blockDim.x) >> 5);

    const float* sp[9];
    int sstr[9], sstep[9], sb_[9], sq_[9];
#pragma unroll
    for (int it = 0; it < 9; it++) {
        uchar4 c = g_ct[it * 32 + lane];
        int sz   = c_SZ[c.x];
        sp[it]   = wb[c.x] + (int)c.y + 2 * gw * sz;
        sstr[it] = sz;
        sstep[it] = 2 * nw * sz;
        sb_[it]  = (int)c.z * 2;
        sq_[it]  = (int)c.w * 2;
    }
    int bquad[3], bfp[3], bpr[3];
#pragma unroll
    for (int it = 0; it < 3; it++) {
        uchar4 c = g_bt[it * 32 + lane];
        bquad[it] = (int)c.x * 4;
        bfp[it]   = (int)c.y * 2;
        bpr[it]   = (int)c.z * 2;
    }

    int e0 = 2 * gw;
    int   nd0n = 0, nd1n = 0;
    float d0n = 0.f, d1n = 0.f;
    if (e0 < E) {
        nd0n = dst[e0];
        d0n  = dist[e0];
        bool v1 = (e0 + 1 < E);
        nd1n = v1 ? dst[e0 + 1] : nd0n;
        d1n  = v1 ? dist[e0 + 1] : d0n;
    }

    for (; e0 < E; e0 += 2 * nw) {
        bool v1 = (e0 + 1 < E);
        int   nd0 = nd0n, nd1 = nd1n;       // this iteration's edge data
        float d0 = d0n, d1 = d1n;

        // ---- 1. issue all wj loads first (addresses independent of dst/dist)
        float w0[9], w1[9];
#pragma unroll
        for (int it = 0; it < 9; it++) {
            w0[it] = __ldcs(sp[it]);
            w1[it] = v1 ? __ldcs(sp[it] + sstr[it]) : 0.f;
            sp[it] += sstep[it];
        }

        // ---- 2. node + LUT loads for current pair (overlap wj latency)
        const float* np0 = g_node + (size_t)nd0 * 36;
        const float* np1 = g_node + (size_t)nd1 * 36;
        float nq0 = np0[lane], nq1 = np1[lane];
        float nx0 = 0.f, nx1 = 0.f;
        if (lane < 4) { nx0 = np0[32 + lane]; nx1 = np1[32 + lane]; }

        float td0 = d0 * (float)NLUT;
        int i00 = max(0, min(NLUT - 1, (int)td0));
        float fr0 = td0 - (float)i00;
        float td1 = d1 * (float)NLUT;
        int i01 = max(0, min(NLUT - 1, (int)td1));
        float fr1 = td1 - (float)i01;
        const float2* Lp0 = (const float2*)g_lut2 + (size_t)i00 * 80;
        const float2* Lp1 = (const float2*)g_lut2 + (size_t)i01 * 80;
        float2 ra[3], rb[3];
#pragma unroll
        for (int it = 0; it < 3; it++) {
            int i = it * 32 + lane;
            if (it < 2 || lane < 12) { ra[it] = Lp0[i]; rb[it] = Lp1[i]; }
        }

        // ---- 3. prefetch next iteration's dst/dist
        int en = e0 + 2 * nw;
        if (en < E) {
            nd0n = dst[en];
            d0n  = dist[en];
            bool vn = (en + 1 < E);
            nd1n = vn ? dst[en + 1] : nd0n;
            d1n  = vn ? dist[en + 1] : d0n;
        }

        // ---- 4. commit node + LUT to smem
        s0[76 + lane] = nq0;
        s1[76 + lane] = nq1;
        if (lane < 4) { s0[108 + lane] = nx0; s1[108 + lane] = nx1; }
#pragma unroll
        for (int it = 0; it < 3; it++) {
            int i = it * 32 + lane;
            if (it < 2 || lane < 12) {
                s0[i] = fmaf(fr0, ra[it].y - ra[it].x, ra[it].x);
                s1[i] = fmaf(fr1, rb[it].y - rb[it].x, rb[it].x);
            }
        }
        __syncwarp();

        // ---- 5. B build (both edges)
#pragma unroll
        for (int it = 0; it < 3; it++) {
            if (it < 2 || lane < 5) {
                float4 Ra = *(const float4*)(s0 + bquad[it]);
                float2 fa = *(const float2*)(s0 + 94 + bfp[it]);
                *(float2*)(s0 + 112 + bpr[it]) =
                    make_float2(Ra.x * fa.x + Ra.y * fa.y, Ra.z * fa.x + Ra.w * fa.y);
                float4 Rb = *(const float4*)(s1 + bquad[it]);
                float2 fb = *(const float2*)(s1 + 94 + bfp[it]);
                *(float2*)(s1 + 112 + bpr[it]) =
                    make_float2(Rb.x * fb.x + Rb.y * fb.y, Rb.z * fb.x + Rb.w * fb.y);
            }
        }
        __syncwarp();

        // ---- 6. contraction (consumes wj values issued at step 1)
        float acc0 = 0.f, acc1 = 0.f;
#pragma unroll
        for (int it = 0; it < 9; it++) {
            bool valid = (it < 8) || (lane < 3);   // 259 = 8*32+3
            float wv0 = valid ? w0[it] : 0.f;
            float wv1 = valid ? w1[it] : 0.f;
            float2 b0 = *(const float2*)(s0 + 112 + sb_[it]);
            float2 q0 = *(const float2*)(s0 + 76 + sq_[it]);
            acc0 = fmaf(wv0, fmaf(q0.x, b0.x, q0.y * b0.y), acc0);
            float2 b1 = *(const float2*)(s1 + 112 + sb_[it]);
            float2 q1 = *(const float2*)(s1 + 76 + sq_[it]);
            acc1 = fmaf(wv1, fmaf(q1.x, b1.x, q1.y * b1.y), acc1);
        }
#pragma unroll
        for (int o = 16; o > 0; o >>= 1) {
            acc0 += __shfl_xor_sync(0xFFFFFFFFu, acc0, o);
            acc1 += __shfl_xor_sync(0xFFFFFFFFu, acc1, o);
        }

        if (lane == 0) {
            float ev0 = expf(acc0);
            eout[e0] = ev0;
            atomicAdd(&g_s[nd0], ev0);
        }
        if (lane == 1 && v1) {
            float ev1 = expf(acc1);
            eout[e0 + 1] = ev1;
            atomicAdd(&g_s[nd1], ev1);
        }
        __syncwarp();
    }
}

__global__ void k_div(const int* __restrict__ dst, float* __restrict__ out, int E) {
    int e = blockIdx.x * blockDim.x + threadIdx.x;
    if (e < E) out[e] = out[e] / g_s[dst[e]];
}

// ---------------------------------------------------------------------------
extern "C" void kernel_launch(void* const* d_in, const int* in_sizes, int n_in,
                              void* d_out, int out_size) {
    int b = (n_in == 26) ? 1 : 0;
    const int*   dst  = (const int*)d_in[b + 0];
    const float* dist = (const float*)d_in[b + 1];
    const float* f0   = (const float*)d_in[b + 2];
    const float* f1   = (const float*)d_in[b + 3];
    const float* f2   = (const float*)d_in[b + 4];
    const float* wq   = (const float*)d_in[b + 5];
    const float* wj[9];
    for (int i = 0; i < 9; i++) wj[i] = (const float*)d_in[b + 6 + i];  // a = k*3+l
    const float* rW1  = (const float*)d_in[b + 15];
    const float* rg1  = (const float*)d_in[b + 17];
    const float* rbb1 = (const float*)d_in[b + 18];
    const float* rW2  = (const float*)d_in[b + 19];
    const float* rb2  = (const float*)d_in[b + 20];
    const float* rg2  = (const float*)d_in[b + 21];
    const float* rbb2 = (const float*)d_in[b + 22];
    const float* rW3  = (const float*)d_in[b + 23];
    const float* rb3  = (const float*)d_in[b + 24];

    int E = in_sizes[b + 0];
    int N = in_sizes[b + 2] / 2;
    float* out = (float*)d_out;

    k_zero<<<256, 256>>>();
    k_tables<<<1, 32>>>();
    k_node<<<(N + 255) / 256, 256>>>(f0, f1, f2, wq, N);
    k_hist<<<296, 256>>>(dist, E);
    k_distmv<<<1, 256>>>(rW1, rg1, rbb1, E);
    k_stats<<<NB / 16, 288>>>(rW2, rb2);
    k_bn2<<<1, 288>>>(rg2, rbb2, E);
    k_lut<<<NLUT + 1, 288>>>(rW2, rb2, rW3, rb3);
    k_main<<<296, 256>>>(dst, dist,
                         wj[0], wj[1], wj[2],
                         wj[3], wj[4], wj[5],
                         wj[6], wj[7], wj[8],
                         out, E);
    k_div<<<(E + 255) / 256, 256>>>(dst, out, E);
}

// round 7
// speedup vs baseline: 3.0615x; 1.0043x over previous
#include <cuda_runtime.h>
#include <math.h>
#include <stdint.h>

// ============================================================================
// AttnBlock: SE(3)-attention edge softmax, D=2, C=2.
//  - radial MLP = scalar piecewise-linear function of dist -> 2048-pt LUT
//    (layer1 BN analytic, layer2 BN via exact per-bin moment histogram).
//  - main kernel: warp per 2 edges, TWO-STAGE software pipeline:
//    node+LUT loads issued one iteration ahead (smem double buffer),
//    dst/dist prefetched two iterations ahead, wj loads same-iteration
//    (covered by compute). All memory latency is cross-iteration.
// ============================================================================

#define NB     2048
#define NLUT   2048
#define NMAX   50048
#define EPSV   1e-5f

__device__ float  g_hist[3 * NB];
__device__ float  g_AB[180];
__device__ double g_stats[540];
__device__ float  g_bn2[540];
__device__ float  g_lut2[(size_t)(NLUT + 1) * 160];  // [i0][i<80][{row i0, row i0+1}]
__device__ float  g_node[(size_t)NMAX * 36];         // qi[18] | fi[18] interleaved pairs
__device__ float  g_s[NMAX];
__device__ uchar4 g_ct[288];   // contraction slot -> (arr, off, b2pair, qpair)
__device__ uchar4 g_bt[96];    // B-build slot -> (Rquad, fpos, b2pair, 0)

__constant__ int c_Roff4[9] = {0, 4, 8, 12, 16, 28, 40, 44, 56}; // p = l*3+k
__constant__ int c_SZ[9]    = {1, 3, 5, 3, 27, 45, 5, 45, 125};  // a = k*3+l

// ---------------------------------------------------------------------------
__global__ void k_init() {
    int i = blockIdx.x * blockDim.x + threadIdx.x;
    int st = gridDim.x * blockDim.x;
    for (int t = i; t < NMAX; t += st)   g_s[t] = 0.f;
    for (int t = i; t < 3 * NB; t += st) g_hist[t] = 0.f;
    for (int t = i; t < 540; t += st)    g_stats[t] = 0.0;
    if (blockIdx.x == 0 && threadIdx.x == 0) {
        const int LOFF2[3] = {0, 1, 4};
        const int FOFF2[3] = {0, 1, 4};
        int PB[9]; int pb = 0;
        for (int a = 0; a < 9; a++) {
            int k = a / 3, l = a % 3;
            int J = 2 * min(k, l) + 1, K2 = 2 * k + 1;
            PB[a] = pb; pb += J * K2;
        }
        int flat = 0;
        for (int a = 0; a < 9; a++) {
            int k = a / 3, l = a % 3;
            int J = 2 * min(k, l) + 1, K2 = 2 * k + 1, L2 = 2 * l + 1;
            int SZ = J * L2 * K2;
            for (int t = 0; t < SZ; t++) {
                int mk = t % K2, r = t / K2, ml = r % L2, j = r / L2;
                uchar4 c;
                c.x = (unsigned char)a;
                c.y = (unsigned char)t;
                c.z = (unsigned char)(PB[a] + j * K2 + mk);
                c.w = (unsigned char)(LOFF2[l] + ml);
                g_ct[flat++] = c;
            }
        }
        for (; flat < 288; flat++) g_ct[flat] = make_uchar4(0, 0, 0, 0);
        int s = 0;
        for (int a = 0; a < 9; a++) {
            int k = a / 3, l = a % 3;
            int J = 2 * min(k, l) + 1, K2 = 2 * k + 1;
            int p = l * 3 + k;
            int quadbase = c_Roff4[p] / 4;
            for (int j = 0; j < J; j++)
                for (int mk = 0; mk < K2; mk++) {
                    uchar4 c;
                    c.x = (unsigned char)(quadbase + j);
                    c.y = (unsigned char)(FOFF2[k] + mk);
                    c.z = (unsigned char)(PB[a] + j * K2 + mk);
                    c.w = 0;
                    g_bt[s++] = c;
                }
        }
        for (; s < 96; s++) g_bt[s] = make_uchar4(0, 0, 0, 0);
    }
}

// Per node: qi[2*m+o] = q[o,m]; fi[2*pos+i] = f-channel i at pos.
__global__ void k_node(const float* __restrict__ f0, const float* __restrict__ f1,
                       const float* __restrict__ f2, const float* __restrict__ wq, int N) {
    int n = blockIdx.x * blockDim.x + threadIdx.x;
    if (n >= N) return;
    const float* F0 = f0 + (size_t)n * 2;
    const float* F1 = f1 + (size_t)n * 6;
    const float* F2 = f2 + (size_t)n * 10;
    float* o_ = g_node + (size_t)n * 36;
#pragma unroll
    for (int o = 0; o < 2; o++) {
        o_[2 * 0 + o] = wq[0 + o * 2 + 0] * F0[0] + wq[0 + o * 2 + 1] * F0[1];
#pragma unroll
        for (int m = 0; m < 3; m++)
            o_[2 * (1 + m) + o] = wq[4 + o * 2 + 0] * F1[m] + wq[4 + o * 2 + 1] * F1[3 + m];
#pragma unroll
        for (int m = 0; m < 5; m++)
            o_[2 * (4 + m) + o] = wq[8 + o * 2 + 0] * F2[m] + wq[8 + o * 2 + 1] * F2[5 + m];
    }
    float* fo = o_ + 18;
#pragma unroll
    for (int i = 0; i < 2; i++) fo[2 * 0 + i] = F0[i];
#pragma unroll
    for (int m = 0; m < 3; m++)
#pragma unroll
        for (int i = 0; i < 2; i++) fo[2 * (1 + m) + i] = F1[i * 3 + m];
#pragma unroll
    for (int m = 0; m < 5; m++)
#pragma unroll
        for (int i = 0; i < 2; i++) fo[2 * (4 + m) + i] = F2[i * 5 + m];
}

__global__ void k_hist(const float* __restrict__ dist, int E) {
    __shared__ float h[3 * NB];
    for (int i = threadIdx.x; i < 3 * NB; i += blockDim.x) h[i] = 0.f;
    __syncthreads();
    int i = blockIdx.x * blockDim.x + threadIdx.x, st = gridDim.x * blockDim.x;
    for (int e = i; e < E; e += st) {
        float d = dist[e];
        int b = (int)(d * (float)NB);
        b = max(0, min(NB - 1, b));
        atomicAdd(&h[b], 1.f);
        atomicAdd(&h[NB + b], d);
        atomicAdd(&h[2 * NB + b], d * d);
    }
    __syncthreads();
    for (int j = threadIdx.x; j < 3 * NB; j += blockDim.x)
        if (h[j] != 0.f) atomicAdd(&g_hist[j], h[j]);
}

__global__ void k_distmv(const float* __restrict__ rW1, const float* __restrict__ rg1,
                         const float* __restrict__ rbb1, int E) {
    __shared__ double rc[256], r1[256], r2[256];
    __shared__ float smu, svar;
    int t = threadIdx.x;
    double c = 0, s1 = 0, s2 = 0;
    for (int b = t; b < NB; b += 256) {
        c  += (double)g_hist[b];
        s1 += (double)g_hist[NB + b];
        s2 += (double)g_hist[2 * NB + b];
    }
    rc[t] = c; r1[t] = s1; r2[t] = s2;
    __syncthreads();
    for (int o = 128; o > 0; o >>= 1) {
        if (t < o) { rc[t] += rc[t + o]; r1[t] += r1[t + o]; r2[t] += r2[t + o]; }
        __syncthreads();
    }
    if (t == 0) {
        double mu  = r1[0] / (double)E;
        double var = r2[0] / (double)E - mu * mu;
        if (var < 0) var = 0;
        smu = (float)mu; svar = (float)var;
    }
    __syncthreads();
    if (t < 90) {
        float w = rW1[t], gi = rg1[t];
        float inv = rsqrtf(svar * w * w + EPSV);
        g_AB[t]      = w * gi * inv;
        g_AB[90 + t] = rbb1[t] - w * smu * gi * inv;
    }
}

__global__ void k_stats(const float* __restrict__ rW2, const float* __restrict__ rb2) {
    __shared__ float sA[90], sB[90];
    int t = threadIdx.x;
    if (t < 90) { sA[t] = g_AB[t]; sB[t] = g_AB[90 + t]; }
    __syncthreads();
    if (t >= 270) return;
    int p = t / 30;
    double s1 = 0, s2 = 0;
    int b0 = blockIdx.x * 16;
    for (int bb = 0; bb < 16; bb++) {
        int b = b0 + bb;
        float cnt = g_hist[b];
        if (cnt == 0.f) continue;
        float m1 = g_hist[NB + b], m2 = g_hist[2 * NB + b];
        float dc = ((float)b + 0.5f) * (1.0f / (float)NB);
        float alpha = rb2[t], beta = 0.f;
#pragma unroll
        for (int u = 0; u < 10; u++) {
            float A = sA[p * 10 + u], Bv = sB[p * 10 + u];
            if (fmaf(A, dc, Bv) > 0.f) {
                float w = rW2[p * 300 + (t - p * 30) * 10 + u];
                alpha = fmaf(w, Bv, alpha);
                beta  = fmaf(w, A,  beta);
            }
        }
        double a = alpha, be = beta;
        s1 += a * (double)cnt + be * (double)m1;
        s2 += a * a * (double)cnt + 2.0 * a * be * (double)m1 + be * be * (double)m2;
    }
    atomicAdd(&g_stats[2 * t],     s1);
    atomicAdd(&g_stats[2 * t + 1], s2);
}

__global__ void k_bn2(const float* __restrict__ rg2, const float* __restrict__ rbb2, int E) {
    int t = threadIdx.x;
    if (t < 270) {
        double mean = g_stats[2 * t] / (double)E;
        double var  = g_stats[2 * t + 1] / (double)E - mean * mean;
        if (var < 0) var = 0;
        float sc = rg2[t] * rsqrtf((float)var + EPSV);
        g_bn2[t]       = sc;
        g_bn2[270 + t] = rbb2[t] - (float)mean * sc;
    }
}

// LUT rows: eval radial at NLUT+1 points; interleaved (row i, row i+1) pairs.
__global__ void k_lut(const float* __restrict__ rW2, const float* __restrict__ rb2,
                      const float* __restrict__ rW3, const float* __restrict__ rb3) {
    __shared__ float h1[90], h2[272];
    int t = threadIdx.x;
    float d = (float)blockIdx.x * (1.0f / (float)NLUT);
    if (t < 90) h1[t] = fmaxf(0.f, fmaf(g_AB[t], d, g_AB[90 + t]));
    __syncthreads();
    if (t < 270) {
        int p = t / 30;
        float z = rb2[t];
#pragma unroll
        for (int u = 0; u < 10; u++)
            z = fmaf(rW2[p * 300 + (t - p * 30) * 10 + u], h1[p * 10 + u], z);
        h2[t] = fmaxf(0.f, fmaf(z, g_bn2[t], g_bn2[270 + t]));
    }
    __syncthreads();
    if (t < 80) {
        float R = 0.f;
        if (t < 76) {
            int p = 0;
#pragma unroll
            for (int pp = 1; pp < 9; pp++) if (t >= c_Roff4[pp]) p = pp;
            int r = t - c_Roff4[p];
            R = rb3[p * 20 + r];
#pragma unroll
            for (int v = 0; v < 30; v++)
                R = fmaf(rW3[p * 600 + r * 30 + v], h2[p * 30 + v], R);
        }
        size_t b = blockIdx.x;
        g_lut2[(b * 80 + t) * 2] = R;
        if (b > 0) g_lut2[((b - 1) * 80 + t) * 2 + 1] = R;
    }
}

// -------- main kernel: warp per 2 edges, 2-stage pipeline ------------------
// per warp: 2 stages x 2 edges x 256 floats.
//   buf: R[0..76) | qi[76..94) | fi[94..112) | B2[112..250)
__global__ void __launch_bounds__(256, 2) k_main(
    const int* __restrict__ dst, const float* __restrict__ dist,
    const float* __restrict__ wa0, const float* __restrict__ wa1,
    const float* __restrict__ wa2, const float* __restrict__ wa3,
    const float* __restrict__ wa4, const float* __restrict__ wa5,
    const float* __restrict__ wa6, const float* __restrict__ wa7,
    const float* __restrict__ wa8,
    float* __restrict__ eout, int E) {
    __shared__ __align__(16) float S[8 * 1024];
    int lane = threadIdx.x & 31;
    float* base = S + ((threadIdx.x >> 5) << 10);

    const float* wb[9] = {wa0, wa1, wa2, wa3, wa4, wa5, wa6, wa7, wa8};

    int gw = (int)((blockIdx.x * blockDim.x + threadIdx.x) >> 5);
    int nw = (int)((gridDim.x * blockDim.x) >> 5);
    int nw2 = 2 * nw;

    const float* sp[9];
    int sstr[9], sb_[9], sq_[9];
#pragma unroll
    for (int it = 0; it < 9; it++) {
        uchar4 c = g_ct[it * 32 + lane];
        int sz   = c_SZ[c.x];
        sp[it]   = wb[c.x] + (int)c.y + 2 * gw * sz;
        sstr[it] = sz;
        sb_[it]  = (int)c.z * 2;
        sq_[it]  = (int)c.w * 2;
    }
    int bquad[3], bfp[3], bpr[3];
#pragma unroll
    for (int it = 0; it < 3; it++) {
        uchar4 c = g_bt[it * 32 + lane];
        bquad[it] = (int)c.x * 4;
        bfp[it]   = (int)c.y * 2;
        bpr[it]   = (int)c.z * 2;
    }

    int e = 2 * gw;
    if (e >= E) return;

    // dst/dist for iter 0 (A) and iter 1 (B)
    int   ndA0 = dst[e];
    float dA0  = dist[e];
    bool  vA   = (e + 1 < E);
    int   ndA1 = vA ? dst[e + 1] : ndA0;
    float dA1  = vA ? dist[e + 1] : dA0;
    int   ndB0 = 0, ndB1 = 0;
    float dB0 = 0.f, dB1 = 0.f;
    {
        int en = e + nw2;
        if (en < E) {
            ndB0 = dst[en];
            dB0  = dist[en];
            bool v = (en + 1 < E);
            ndB1 = v ? dst[en + 1] : ndB0;
            dB1  = v ? dist[en + 1] : dB0;
        }
    }

    // prologue: fill stage 0 with iter-0 node+LUT
    {
        float* s0 = base;
        float* s1 = base + 256;
        const float* np0 = g_node + (size_t)ndA0 * 36;
        const float* np1 = g_node + (size_t)ndA1 * 36;
        s0[76 + lane] = np0[lane];
        s1[76 + lane] = np1[lane];
        if (lane < 4) { s0[108 + lane] = np0[32 + lane]; s1[108 + lane] = np1[32 + lane]; }
        float td0 = dA0 * (float)NLUT;
        int i00 = max(0, min(NLUT - 1, (int)td0));
        float fr0 = td0 - (float)i00;
        float td1 = dA1 * (float)NLUT;
        int i01 = max(0, min(NLUT - 1, (int)td1));
        float fr1 = td1 - (float)i01;
        const float2* Lp0 = (const float2*)g_lut2 + (size_t)i00 * 80;
        const float2* Lp1 = (const float2*)g_lut2 + (size_t)i01 * 80;
#pragma unroll
        for (int it = 0; it < 3; it++) {
            int i = it * 32 + lane;
            if (it < 2 || lane < 12) {
                float2 ra = Lp0[i], rb = Lp1[i];
                s0[i] = fmaf(fr0, ra.y - ra.x, ra.x);
                s1[i] = fmaf(fr1, rb.y - rb.x, rb.x);
            }
        }
    }

    int p = 0;
    for (; e < E; e += nw2, p ^= 1) {
        float* s0 = base + (p << 9);
        float* s1 = s0 + 256;
        float* t0 = base + ((p ^ 1) << 9);
        float* t1 = t0 + 256;
        bool v1 = (e + 1 < E);

        // ---- 1. wj loads for THIS iteration (covered by compute below)
        float w0[9], w1[9];
#pragma unroll
        for (int it = 0; it < 9; it++) {
            w0[it] = __ldcs(sp[it]);
            w1[it] = v1 ? __ldcs(sp[it] + sstr[it]) : 0.f;
            sp[it] += sstr[it] * nw2;
        }

        // ---- 2. issue node+LUT loads for NEXT iteration (dst/dist already here)
        const float* np0 = g_node + (size_t)ndB0 * 36;
        const float* np1 = g_node + (size_t)ndB1 * 36;
        float nq0 = np0[lane], nq1 = np1[lane];
        float nx0 = 0.f, nx1 = 0.f;
        if (lane < 4) { nx0 = np0[32 + lane]; nx1 = np1[32 + lane]; }
        float tdb0 = dB0 * (float)NLUT;
        int ib0 = max(0, min(NLUT - 1, (int)tdb0));
        float frb0 = tdb0 - (float)ib0;
        float tdb1 = dB1 * (float)NLUT;
        int ib1 = max(0, min(NLUT - 1, (int)tdb1));
        float frb1 = tdb1 - (float)ib1;
        const float2* LpB0 = (const float2*)g_lut2 + (size_t)ib0 * 80;
        const float2* LpB1 = (const float2*)g_lut2 + (size_t)ib1 * 80;
        float2 ra[3], rb[3];
#pragma unroll
        for (int it = 0; it < 3; it++) {
            int i = it * 32 + lane;
            if (it < 2 || lane < 12) { ra[it] = LpB0[i]; rb[it] = LpB1[i]; }
        }

        // ---- 3. prefetch dst/dist two iterations ahead
        int   ndC0 = 0, ndC1 = 0;
        float dC0 = 0.f, dC1 = 0.f;
        {
            int e2 = e + 2 * nw2;
            if (e2 < E) {
                ndC0 = dst[e2];
                dC0  = dist[e2];
                bool v = (e2 + 1 < E);
                ndC1 = v ? dst[e2 + 1] : ndC0;
                dC1  = v ? dist[e2 + 1] : dC0;
            }
        }

        // ---- 4. sync: stage-p buffers (committed last iteration) are ready
        __syncwarp();

        // ---- 5a. B build in stage p
#pragma unroll
        for (int it = 0; it < 3; it++) {
            if (it < 2 || lane < 5) {
                float4 Ra = *(const float4*)(s0 + bquad[it]);
                float2 fa = *(const float2*)(s0 + 94 + bfp[it]);
                *(float2*)(s0 + 112 + bpr[it]) =
                    make_float2(Ra.x * fa.x + Ra.y * fa.y, Ra.z * fa.x + Ra.w * fa.y);
                float4 Rb = *(const float4*)(s1 + bquad[it]);
                float2 fb = *(const float2*)(s1 + 94 + bfp[it]);
                *(float2*)(s1 + 112 + bpr[it]) =
                    make_float2(Rb.x * fb.x + Rb.y * fb.y, Rb.z * fb.x + Rb.w * fb.y);
            }
        }
        __syncwarp();

        // ---- 5b. contraction + reduce + output
        float acc0 = 0.f, acc1 = 0.f;
#pragma unroll
        for (int it = 0; it < 9; it++) {
            bool valid = (it < 8) || (lane < 3);   // 259 = 8*32+3
            float wv0 = valid ? w0[it] : 0.f;
            float wv1 = valid ? w1[it] : 0.f;
            float2 b0 = *(const float2*)(s0 + 112 + sb_[it]);
            float2 q0 = *(const float2*)(s0 + 76 + sq_[it]);
            acc0 = fmaf(wv0, fmaf(q0.x, b0.x, q0.y * b0.y), acc0);
            float2 b1 = *(const float2*)(s1 + 112 + sb_[it]);
            float2 q1 = *(const float2*)(s1 + 76 + sq_[it]);
            acc1 = fmaf(wv1, fmaf(q1.x, b1.x, q1.y * b1.y), acc1);
        }
#pragma unroll
        for (int o = 16; o > 0; o >>= 1) {
            acc0 += __shfl_xor_sync(0xFFFFFFFFu, acc0, o);
            acc1 += __shfl_xor_sync(0xFFFFFFFFu, acc1, o);
        }
        if (lane == 0) {
            float ev0 = expf(acc0);
            eout[e] = ev0;
            atomicAdd(&g_s[ndA0], ev0);
        }
        if (lane == 1 && v1) {
            float ev1 = expf(acc1);
            eout[e + 1] = ev1;
            atomicAdd(&g_s[ndA1], ev1);
        }

        // ---- 6. commit next iteration's node+LUT into stage p^1
        t0[76 + lane] = nq0;
        t1[76 + lane] = nq1;
        if (lane < 4) { t0[108 + lane] = nx0; t1[108 + lane] = nx1; }
#pragma unroll
        for (int it = 0; it < 3; it++) {
            int i = it * 32 + lane;
            if (it < 2 || lane < 12) {
                t0[i] = fmaf(frb0, ra[it].y - ra[it].x, ra[it].x);
                t1[i] = fmaf(frb1, rb[it].y - rb[it].x, rb[it].x);
            }
        }

        // ---- 7. rotate edge metadata
        ndA0 = ndB0; ndA1 = ndB1; dA0 = dB0; dA1 = dB1;
        ndB0 = ndC0; ndB1 = ndC1; dB0 = dC0; dB1 = dC1;
    }
}

__global__ void k_div(const int* __restrict__ dst, float* __restrict__ out, int E) {
    int e = blockIdx.x * blockDim.x + threadIdx.x;
    if (e < E) out[e] = out[e] / g_s[dst[e]];
}

// ---------------------------------------------------------------------------
extern "C" void kernel_launch(void* const* d_in, const int* in_sizes, int n_in,
                              void* d_out, int out_size) {
    int b = (n_in == 26) ? 1 : 0;
    const int*   dst  = (const int*)d_in[b + 0];
    const float* dist = (const float*)d_in[b + 1];
    const float* f0   = (const float*)d_in[b + 2];
    const float* f1   = (const float*)d_in[b + 3];
    const float* f2   = (const float*)d_in[b + 4];
    const float* wq   = (const float*)d_in[b + 5];
    const float* wj[9];
    for (int i = 0; i < 9; i++) wj[i] = (const float*)d_in[b + 6 + i];  // a = k*3+l
    const float* rW1  = (const float*)d_in[b + 15];
    const float* rg1  = (const float*)d_in[b + 17];
    const float* rbb1 = (const float*)d_in[b + 18];
    const float* rW2  = (const float*)d_in[b + 19];
    const float* rb2  = (const float*)d_in[b + 20];
    const float* rg2  = (const float*)d_in[b + 21];
    const float* rbb2 = (const float*)d_in[b + 22];
    const float* rW3  = (const float*)d_in[b + 23];
    const float* rb3  = (const float*)d_in[b + 24];

    int E = in_sizes[b + 0];
    int N = in_sizes[b + 2] / 2;
    float* out = (float*)d_out;

    k_init<<<256, 256>>>();
    k_node<<<(N + 255) / 256, 256>>>(f0, f1, f2, wq, N);
    k_hist<<<296, 256>>>(dist, E);
    k_distmv<<<1, 256>>>(rW1, rg1, rbb1, E);
    k_stats<<<NB / 16, 288>>>(rW2, rb2);
    k_bn2<<<1, 288>>>(rg2, rbb2, E);
    k_lut<<<NLUT + 1, 288>>>(rW2, rb2, rW3, rb3);
    k_main<<<296, 256>>>(dst, dist,
                         wj[0], wj[1], wj[2],
                         wj[3], wj[4], wj[5],
                         wj[6], wj[7], wj[8],
                         out, E);
    k_div<<<(E + 255) / 256, 256>>>(dst, out, E);
}